// round 2
// baseline (speedup 1.0000x reference)
#include <cuda_runtime.h>

// Problem constants (fixed by the reference)
#define NB 8192   // batch
#define ND 1024   // in_dim
#define NH 1024   // hidden = max(64, D)
#define NE 8      // experts
#define NK 5      // depth classes
#define NKM1 4    // K-1 ordinal logits

#define TM 64     // tokens per block
#define TN 64     // hidden chunk per iteration
#define BK 16     // k-step
#define PAD 68    // padded row length for smem tiles (bank-conflict + float4 alignment)
#define EPSV 1e-8f

// -------- device scratch (no allocations allowed) --------
__device__ int g_odd_or;
__device__ int g_cursor[NE];
__device__ int g_perm[NE * NB];

// -------- routing kernels --------
__global__ void k_init() {
    if (threadIdx.x == 0) g_odd_or = 0;
    if (threadIdx.x < NE) g_cursor[threadIdx.x] = 0;
}

// Detect whether size_idx is int64 (odd int32 slots all zero) or int32.
__global__ void k_detect(const int* __restrict__ s) {
    int i = blockIdx.x * blockDim.x + threadIdx.x;   // 0..4095
    int v = s[2 * i + 1];
    unsigned any = __ballot_sync(0xFFFFFFFFu, v != 0);
    if ((threadIdx.x & 31) == 0 && any) atomicOr(&g_odd_or, 1);
}

// Scatter token ids into per-expert buckets.
__global__ void k_route(const int* __restrict__ s) {
    int b = blockIdx.x * blockDim.x + threadIdx.x;   // 0..8191
    if (b >= NB) return;
    int is64 = (g_odd_or == 0);
    int e = is64 ? s[2 * b] : s[b];
    e &= (NE - 1);  // safety clamp
    int pos = atomicAdd(&g_cursor[e], 1);
    g_perm[e * NB + pos] = b;
}

// -------- fused expert MLP + ordinal head --------
// Block: 64 tokens of one expert. Loop hidden dim in chunks of 64:
//   h_chunk = relu(x_tile @ W1[e][:, hc:hc+64] + b1)  (fp32 SIMT GEMM)
//   logits += h_chunk @ W2[e][hc:hc+64, :]
// Epilogue: +b2, write logits, compute ordinal probs, write probs.
__global__ __launch_bounds__(256) void k_main(
    const float* __restrict__ x,
    const float* __restrict__ W1,
    const float* __restrict__ b1,
    const float* __restrict__ W2,
    const float* __restrict__ b2,
    float* __restrict__ out)
{
    const int e = blockIdx.y;
    const int cnt = g_cursor[e];
    const int t0 = blockIdx.x * TM;
    if (t0 >= cnt) return;

    const int tid = threadIdx.x;
    const int ty = tid >> 4;    // 0..15 (token-dir)
    const int tx = tid & 15;    // 0..15 (hidden-dir)

    __shared__ float xs[BK][PAD];     // x   staged transposed: [kk][m]
    __shared__ float ws[BK][PAD];     // W1  staged:            [kk][n]
    __shared__ float hs[TM][PAD];     // relu'd hidden chunk:   [m][n]
    __shared__ float w2s[TN][NKM1];   // W2 chunk
    __shared__ float lgs[TM][NKM1];   // final logits
    __shared__ int   toks[TM];

    if (tid < TM) {
        int m = t0 + tid;
        toks[tid] = (m < cnt) ? g_perm[e * NB + m] : -1;
    }
    __syncthreads();

    const float* __restrict__ W1e = W1 + (size_t)e * ND * NH;
    float lg = 0.0f;   // this thread's logit partial: token i = tid>>2, class k = tid&3

    for (int hc = 0; hc < NH; hc += TN) {
        float acc[4][4];
        #pragma unroll
        for (int a = 0; a < 4; a++)
            #pragma unroll
            for (int b = 0; b < 4; b++) acc[a][b] = 0.0f;

        // load W2 chunk (256 threads == 64*4 elements)
        {
            int hn = tid >> 2, k = tid & 3;
            w2s[hn][k] = W2[((size_t)e * NH + hc + hn) * NKM1 + k];
        }

        for (int k0 = 0; k0 < ND; k0 += BK) {
            __syncthreads();
            // fill xs[kk][m]: 16 consecutive threads read 16 consecutive d of one token
            {
                int kk = tid & 15;
                int mb = tid >> 4;
                #pragma unroll
                for (int r = 0; r < 4; r++) {
                    int m = mb + 16 * r;
                    int tk = toks[m];
                    xs[kk][m] = (tk >= 0) ? __ldg(&x[(size_t)tk * ND + k0 + kk]) : 0.0f;
                }
            }
            // fill ws[kk][n]: 64 consecutive threads read 64 consecutive h
            {
                int n  = tid & 63;
                int kb = tid >> 6;   // 0..3
                #pragma unroll
                for (int r = 0; r < 4; r++) {
                    int kk = kb + 4 * r;
                    ws[kk][n] = __ldg(&W1e[(size_t)(k0 + kk) * NH + hc + n]);
                }
            }
            __syncthreads();

            #pragma unroll
            for (int kk = 0; kk < BK; kk++) {
                float4 xv = *(const float4*)&xs[kk][ty * 4];
                float4 wv = *(const float4*)&ws[kk][tx * 4];
                acc[0][0] += xv.x * wv.x; acc[0][1] += xv.x * wv.y;
                acc[0][2] += xv.x * wv.z; acc[0][3] += xv.x * wv.w;
                acc[1][0] += xv.y * wv.x; acc[1][1] += xv.y * wv.y;
                acc[1][2] += xv.y * wv.z; acc[1][3] += xv.y * wv.w;
                acc[2][0] += xv.z * wv.x; acc[2][1] += xv.z * wv.y;
                acc[2][2] += xv.z * wv.z; acc[2][3] += xv.z * wv.w;
                acc[3][0] += xv.w * wv.x; acc[3][1] += xv.w * wv.y;
                acc[3][2] += xv.w * wv.z; acc[3][3] += xv.w * wv.w;
            }
        }

        // bias + relu -> hs
        #pragma unroll
        for (int a = 0; a < 4; a++) {
            int m = ty * 4 + a;
            #pragma unroll
            for (int b = 0; b < 4; b++) {
                int n = tx * 4 + b;
                float v = acc[a][b] + b1[e * NH + hc + n];
                hs[m][n] = fmaxf(v, 0.0f);
            }
        }
        __syncthreads();

        // layer-2 partial: thread (i = tid>>2, k = tid&3)
        {
            int i = tid >> 2, k = tid & 3;
            float s = 0.0f;
            #pragma unroll
            for (int hn = 0; hn < TN; hn++)
                s += hs[i][hn] * w2s[hn][k];
            lg += s;
        }
        __syncthreads();  // protect hs / w2s before next chunk
    }

    // epilogue: +b2, write logits
    {
        int i = tid >> 2, k = tid & 3;
        lg += b2[e * NKM1 + k];
        lgs[i][k] = lg;
        int tk = toks[i];
        if (tk >= 0)
            out[(size_t)tk * NKM1 + k] = lg;
    }
    __syncthreads();

    // ordinal probs: one thread per token
    if (tid < TM) {
        int tk = toks[tid];
        if (tk >= 0) {
            float q0 = 1.0f / (1.0f + expf(-lgs[tid][0]));
            float q1 = 1.0f / (1.0f + expf(-lgs[tid][1]));
            float q2 = 1.0f / (1.0f + expf(-lgs[tid][2]));
            float q3 = 1.0f / (1.0f + expf(-lgs[tid][3]));
            float p[NK];
            p[0] = 1.0f - q0;
            p[1] = q0 - q1;
            p[2] = q1 - q2;
            p[3] = q2 - q3;
            p[4] = q3;
            float ssum = 0.0f;
            #pragma unroll
            for (int k = 0; k < NK; k++) { p[k] = fmaxf(p[k], EPSV); ssum += p[k]; }
            ssum = fmaxf(ssum, EPSV);
            float inv = 1.0f / ssum;
            float* po = out + (size_t)NB * NKM1 + (size_t)tk * NK;
            #pragma unroll
            for (int k = 0; k < NK; k++) po[k] = p[k] * inv;
        }
    }
}

extern "C" void kernel_launch(void* const* d_in, const int* in_sizes, int n_in,
                              void* d_out, int out_size) {
    const float* x   = (const float*)d_in[0];
    const int*   sidx = (const int*)d_in[1];   // int32 or int64 (auto-detected)
    const float* W1  = (const float*)d_in[2];
    const float* b1  = (const float*)d_in[3];
    const float* W2  = (const float*)d_in[4];
    const float* b2  = (const float*)d_in[5];
    float* out = (float*)d_out;

    k_init<<<1, 64>>>();
    k_detect<<<16, 256>>>(sidx);
    k_route<<<32, 256>>>(sidx);
    k_main<<<dim3(NB / TM, NE), 256>>>(x, W1, b1, W2, b2, out);
}

// round 7
// speedup vs baseline: 8.0644x; 8.0644x over previous
#include <cuda_runtime.h>
#include <cuda_bf16.h>
#include <cstdint>

// ---------------- problem constants ----------------
#define NB 8192   // batch
#define ND 1024   // in_dim
#define NH 1024   // hidden
#define NE 8      // experts
#define NK 5
#define NKM1 4
#define EPSV 1e-8f

// ---------------- GEMM tiling ----------------
#define TMT 128          // token tile (M)
#define TNT 128          // hidden tile (N)
#define KCH 32           // K elements per chunk (64B bf16)
#define NCH 96           // 3 * ND / KCH  (bf16x3 -> K' = 3072)
#define STAGES 4
#define ASTRIDE 80       // padded smem row stride (bytes): conflict-free ldmatrix

// ---------------- smem layout (bytes, dynamic) ----------------
#define SA(s)   ((s) * 10240)               // 128 rows * 80B
#define SB(s)   (40960 + (s) * 10240)
#define SM_B1S  81920                        // 128 f32
#define SM_W2S  82432                        // 128*4 f32
#define SM_RED  84480                        // 2*4*64*4 f32 = 8KB
#define SM_TOT  92672

// ---------------- device scratch ----------------
__device__ int g_odd_or;
__device__ int g_cursor[NE];
__device__ int g_off[NE + 1];
__device__ int g_perm[NE * NB];
__device__ __nv_bfloat16 g_Xh[(size_t)NB * ND];
__device__ __nv_bfloat16 g_Xl[(size_t)NB * ND];
__device__ __nv_bfloat16 g_Wh[(size_t)NE * NH * ND];   // W1^T [e][n][k]
__device__ __nv_bfloat16 g_Wl[(size_t)NE * NH * ND];
__device__ float g_partial[(size_t)NB * 32];           // [p][ntile(8)][k(4)]

// ---------------- PTX helpers (all plain sm_80-era) ----------------
__device__ __forceinline__ uint32_t smem_u32(const void* p) {
    uint32_t a;
    asm("{ .reg .u64 t; cvta.to.shared.u64 t, %1; cvt.u32.u64 %0, t; }" : "=r"(a) : "l"(p));
    return a;
}
__device__ __forceinline__ void cp16(uint32_t dst, const void* src) {
    asm volatile("cp.async.cg.shared.global [%0], [%1], 16;" :: "r"(dst), "l"(src));
}
__device__ __forceinline__ void cp_commit() {
    asm volatile("cp.async.commit_group;" ::: "memory");
}
template <int N> __device__ __forceinline__ void cp_wait() {
    asm volatile("cp.async.wait_group %0;" :: "n"(N) : "memory");
}
__device__ __forceinline__ void ldsm4(uint32_t& r0, uint32_t& r1, uint32_t& r2, uint32_t& r3,
                                      uint32_t addr) {
    asm volatile("ldmatrix.sync.aligned.m8n8.x4.shared.b16 {%0,%1,%2,%3}, [%4];"
                 : "=r"(r0), "=r"(r1), "=r"(r2), "=r"(r3) : "r"(addr));
}
__device__ __forceinline__ void mma_bf16(float* d, const uint32_t* a, const uint32_t* b) {
    asm volatile(
        "mma.sync.aligned.m16n8k16.row.col.f32.bf16.bf16.f32 "
        "{%0,%1,%2,%3}, {%4,%5,%6,%7}, {%8,%9}, {%0,%1,%2,%3};"
        : "+f"(d[0]), "+f"(d[1]), "+f"(d[2]), "+f"(d[3])
        : "r"(a[0]), "r"(a[1]), "r"(a[2]), "r"(a[3]), "r"(b[0]), "r"(b[1]));
}

// ---------------- routing ----------------
__global__ void k_init() {
    if (threadIdx.x == 0) g_odd_or = 0;
    if (threadIdx.x < NE) g_cursor[threadIdx.x] = 0;
}
__global__ void k_detect(const int* __restrict__ s) {
    int i = blockIdx.x * blockDim.x + threadIdx.x;
    int v = s[2 * i + 1];
    unsigned any = __ballot_sync(0xFFFFFFFFu, v != 0);
    if ((threadIdx.x & 31) == 0 && any) atomicOr(&g_odd_or, 1);
}
__global__ void k_route(const int* __restrict__ s) {
    int b = blockIdx.x * blockDim.x + threadIdx.x;
    if (b >= NB) return;
    int e = (g_odd_or == 0) ? s[2 * b] : s[b];
    e &= (NE - 1);
    int pos = atomicAdd(&g_cursor[e], 1);
    g_perm[e * NB + pos] = b;
}
__global__ void k_offsets() {
    if (threadIdx.x == 0) {
        int s = 0;
        for (int e = 0; e < NE; e++) { g_off[e] = s; s += g_cursor[e]; }
        g_off[NE] = s;
    }
}

// ---------------- conversion ----------------
__global__ __launch_bounds__(128) void k_convert_x(const float* __restrict__ x) {
    int p = blockIdx.x;
    int tid = threadIdx.x;
    int e = 0;
    #pragma unroll
    for (int q = 0; q < NE - 1; q++) if (p >= g_off[q + 1]) e = q + 1;
    int tok = g_perm[e * NB + (p - g_off[e])];
    const float4* src = (const float4*)(x + (size_t)tok * ND);
    __nv_bfloat162* dh = (__nv_bfloat162*)(g_Xh + (size_t)p * ND);
    __nv_bfloat162* dl = (__nv_bfloat162*)(g_Xl + (size_t)p * ND);
    #pragma unroll
    for (int j = 0; j < 2; j++) {
        int idx = tid + j * 128;
        float4 v = __ldg(src + idx);
        __nv_bfloat16 h0 = __float2bfloat16(v.x), h1 = __float2bfloat16(v.y);
        __nv_bfloat16 h2 = __float2bfloat16(v.z), h3 = __float2bfloat16(v.w);
        __nv_bfloat16 l0 = __float2bfloat16(v.x - __bfloat162float(h0));
        __nv_bfloat16 l1 = __float2bfloat16(v.y - __bfloat162float(h1));
        __nv_bfloat16 l2 = __float2bfloat16(v.z - __bfloat162float(h2));
        __nv_bfloat16 l3 = __float2bfloat16(v.w - __bfloat162float(h3));
        dh[idx * 2 + 0] = __nv_bfloat162{h0, h1};
        dh[idx * 2 + 1] = __nv_bfloat162{h2, h3};
        dl[idx * 2 + 0] = __nv_bfloat162{l0, l1};
        dl[idx * 2 + 1] = __nv_bfloat162{l2, l3};
    }
}
__global__ __launch_bounds__(256) void k_convert_w(const float* __restrict__ W1) {
    __shared__ float t[32][33];
    int e = blockIdx.z;
    int n0 = blockIdx.x * 32, k0 = blockIdx.y * 32;
    int tx = threadIdx.x, ty = threadIdx.y;
    #pragma unroll
    for (int j = 0; j < 4; j++) {
        int k = k0 + ty + j * 8;
        t[ty + j * 8][tx] = __ldg(&W1[((size_t)e * ND + k) * NH + n0 + tx]);
    }
    __syncthreads();
    #pragma unroll
    for (int j = 0; j < 4; j++) {
        int n = n0 + ty + j * 8;
        float v = t[tx][ty + j * 8];
        __nv_bfloat16 h = __float2bfloat16(v);
        __nv_bfloat16 l = __float2bfloat16(v - __bfloat162float(h));
        size_t o = ((size_t)e * NH + n) * ND + k0 + tx;
        g_Wh[o] = h;
        g_Wl[o] = l;
    }
}

// ---------------- grouped GEMM (mma.sync bf16x3) + fused epilogue ----------------
// CTA: 128 tokens x 128 hidden for expert e; 8 warps in 2(M) x 4(N) grid,
// warp tile 64x32, mma m16n8k16, cp.async 4-stage pipeline, K' = 3072.
__global__ __launch_bounds__(256, 2) void k_gemm(const float* __restrict__ b1,
                                                 const float* __restrict__ W2) {
    const int mt = blockIdx.x, nt = blockIdx.y, e = blockIdx.z;
    const int cnt = g_cursor[e];
    if (mt * TMT >= cnt) return;

    extern __shared__ char smem[];
    const uint32_t sb = smem_u32(smem);
    const int tid = threadIdx.x;
    const int lane = tid & 31, warp = tid >> 5;
    const int wm = warp >> 2, wn = warp & 3;

    float* b1s = (float*)(smem + SM_B1S);
    float* w2s = (float*)(smem + SM_W2S);
    float* red = (float*)(smem + SM_RED);

    if (tid < 128) b1s[tid] = b1[e * NH + nt * TNT + tid];
    #pragma unroll
    for (int j = 0; j < 2; j++) {
        int idx = tid + j * 256;
        w2s[idx] = W2[((size_t)e * NH + nt * TNT) * NKM1 + idx];
    }

    const int aBase = g_off[e] + mt * TMT;
    const int bBase = e * NH + nt * TNT;

    // ldmatrix lane-address offsets
    const uint32_t aRowOff = (uint32_t)(wm * 64 + (lane & 15)) * ASTRIDE + ((lane >> 4) * 16);
    const uint32_t bRowOff = (uint32_t)(wn * 32 + (lane & 7) + ((lane >> 4) & 1) * 8) * ASTRIDE +
                             (((lane >> 3) & 1) * 16);

    float acc[4][4][4];
    #pragma unroll
    for (int i = 0; i < 4; i++)
        #pragma unroll
        for (int j = 0; j < 4; j++)
            #pragma unroll
            for (int r = 0; r < 4; r++) acc[i][j][r] = 0.0f;

    auto load_stage = [&](int c, int st) {
        const int seg = c >> 5;
        const int kc = (c & 31) << 5;   // K offset in elements
        const __nv_bfloat16* __restrict__ As = (seg == 1) ? g_Xl : g_Xh;
        const __nv_bfloat16* __restrict__ Bs = (seg == 2) ? g_Wl : g_Wh;
        #pragma unroll
        for (int j = 0; j < 2; j++) {
            int idx = tid + j * 256;        // 0..511
            int row = idx >> 2, ch = idx & 3;
            int gr = aBase + row; if (gr > NB - 1) gr = NB - 1;
            cp16(sb + SA(st) + row * ASTRIDE + ch * 16,
                 As + (size_t)gr * ND + kc + ch * 8);
            cp16(sb + SB(st) + row * ASTRIDE + ch * 16,
                 Bs + (size_t)(bBase + row) * ND + kc + ch * 8);
        }
    };

    // prologue: 3 stages in flight
    #pragma unroll
    for (int c = 0; c < 3; c++) { load_stage(c, c); cp_commit(); }

    for (int c = 0; c < NCH; c++) {
        cp_wait<2>();
        __syncthreads();
        const int st = c & (STAGES - 1);
        const uint32_t sA = sb + SA(st), sBt = sb + SB(st);

        #pragma unroll
        for (int ks = 0; ks < 2; ks++) {
            uint32_t bf[4][2];
            #pragma unroll
            for (int ntp = 0; ntp < 2; ntp++) {
                ldsm4(bf[2 * ntp][0], bf[2 * ntp][1], bf[2 * ntp + 1][0], bf[2 * ntp + 1][1],
                      sBt + bRowOff + ntp * (16 * ASTRIDE) + ks * 32);
            }
            uint32_t af[4][4];
            #pragma unroll
            for (int m = 0; m < 4; m++) {
                ldsm4(af[m][0], af[m][1], af[m][2], af[m][3],
                      sA + aRowOff + m * (16 * ASTRIDE) + ks * 32);
            }
            #pragma unroll
            for (int m = 0; m < 4; m++)
                #pragma unroll
                for (int n = 0; n < 4; n++)
                    mma_bf16(acc[m][n], af[m], bf[n]);
        }

        __syncthreads();
        if (c + 3 < NCH) load_stage(c + 3, (c + 3) & (STAGES - 1));
        cp_commit();
    }
    cp_wait<0>();

    // ---------- fused epilogue: bias + relu + W2 contraction ----------
    #pragma unroll
    for (int m = 0; m < 4; m++) {
        float pr[2][4] = {{0.f, 0.f, 0.f, 0.f}, {0.f, 0.f, 0.f, 0.f}};
        #pragma unroll
        for (int n = 0; n < 4; n++) {
            #pragma unroll
            for (int r = 0; r < 4; r++) {
                int col = wn * 32 + n * 8 + 2 * (lane & 3) + (r & 1);
                float v = acc[m][n][r] + b1s[col];
                v = fmaxf(v, 0.0f);
                int half = r >> 1;
                #pragma unroll
                for (int k = 0; k < 4; k++) pr[half][k] += v * w2s[col * 4 + k];
            }
        }
        #pragma unroll
        for (int h = 0; h < 2; h++)
            #pragma unroll
            for (int k = 0; k < 4; k++) {
                pr[h][k] += __shfl_xor_sync(0xFFFFFFFFu, pr[h][k], 1);
                pr[h][k] += __shfl_xor_sync(0xFFFFFFFFu, pr[h][k], 2);
            }
        if ((lane & 3) == 0) {
            int r0 = m * 16 + (lane >> 2);
            float* dst0 = &red[(((wm * 4 + wn) * 64) + r0) * 4];
            float* dst1 = &red[(((wm * 4 + wn) * 64) + r0 + 8) * 4];
            #pragma unroll
            for (int k = 0; k < 4; k++) { dst0[k] = pr[0][k]; dst1[k] = pr[1][k]; }
        }
    }
    __syncthreads();

    // cross-warp(N) reduction + store partials (deterministic order)
    #pragma unroll
    for (int j = 0; j < 2; j++) {
        int idx = tid + j * 256;          // 0..511 : (row 0..127, k 0..3)
        int row = idx >> 2, k = idx & 3;
        int wmr = row >> 6, r64 = row & 63;
        float s = 0.f;
        #pragma unroll
        for (int w = 0; w < 4; w++) s += red[(((wmr * 4 + w) * 64) + r64) * 4 + k];
        if (mt * TMT + row < cnt) {
            int p = aBase + row;
            g_partial[(size_t)p * 32 + nt * 4 + k] = s;
        }
    }
}

// ---------------- final reduction + ordinal head ----------------
__global__ __launch_bounds__(256) void k_final(const float* __restrict__ b2,
                                               float* __restrict__ out) {
    int p = blockIdx.x * blockDim.x + threadIdx.x;
    if (p >= NB) return;
    int e = 0;
    #pragma unroll
    for (int q = 0; q < NE - 1; q++) if (p >= g_off[q + 1]) e = q + 1;
    int tok = g_perm[e * NB + (p - g_off[e])];

    float lg[NKM1];
    #pragma unroll
    for (int k = 0; k < NKM1; k++) {
        float s = b2[e * NKM1 + k];
        #pragma unroll
        for (int ntl = 0; ntl < 8; ntl++) s += g_partial[(size_t)p * 32 + ntl * 4 + k];
        lg[k] = s;
        out[(size_t)tok * NKM1 + k] = s;
    }
    float q0 = 1.0f / (1.0f + expf(-lg[0]));
    float q1 = 1.0f / (1.0f + expf(-lg[1]));
    float q2 = 1.0f / (1.0f + expf(-lg[2]));
    float q3 = 1.0f / (1.0f + expf(-lg[3]));
    float pr[NK];
    pr[0] = 1.0f - q0; pr[1] = q0 - q1; pr[2] = q1 - q2; pr[3] = q2 - q3; pr[4] = q3;
    float ssum = 0.0f;
    #pragma unroll
    for (int k = 0; k < NK; k++) { pr[k] = fmaxf(pr[k], EPSV); ssum += pr[k]; }
    ssum = fmaxf(ssum, EPSV);
    float inv = 1.0f / ssum;
    float* po = out + (size_t)NB * NKM1 + (size_t)tok * NK;
    #pragma unroll
    for (int k = 0; k < NK; k++) po[k] = pr[k] * inv;
}

// ---------------- launch ----------------
extern "C" void kernel_launch(void* const* d_in, const int* in_sizes, int n_in,
                              void* d_out, int out_size) {
    const float* x    = (const float*)d_in[0];
    const int*   sidx = (const int*)d_in[1];
    const float* W1   = (const float*)d_in[2];
    const float* b1   = (const float*)d_in[3];
    const float* W2   = (const float*)d_in[4];
    const float* b2   = (const float*)d_in[5];
    float* out = (float*)d_out;

    cudaFuncSetAttribute(k_gemm, cudaFuncAttributeMaxDynamicSharedMemorySize, SM_TOT);

    k_init<<<1, 64>>>();
    k_detect<<<16, 256>>>(sidx);
    k_route<<<32, 256>>>(sidx);
    k_offsets<<<1, 32>>>();
    k_convert_x<<<NB, 128>>>(x);
    k_convert_w<<<dim3(32, 32, 8), dim3(32, 8)>>>(W1);
    k_gemm<<<dim3(NB / TMT, NH / TNT, NE), 256, SM_TOT>>>(b1, W2);
    k_final<<<NB / 256, 256>>>(b2, out);
}

// round 8
// speedup vs baseline: 8.8799x; 1.1011x over previous
#include <cuda_runtime.h>
#include <cuda_bf16.h>
#include <cstdint>

// ---------------- problem constants ----------------
#define NB 8192
#define ND 1024
#define NH 1024
#define NE 8
#define NK 5
#define NKM1 4
#define EPSV 1e-8f

// ---------------- GEMM tiling ----------------
#define TMT 128          // token tile (M)
#define TNT 256          // hidden tile (N)
#define KCH 32           // K elements per chunk (64B bf16)
#define NCH 96           // 3 * ND / KCH  (bf16x3 -> K' = 3072)
#define STAGES 5
#define ASTRIDE 80       // padded smem row stride (bytes)

// ---------------- smem layout (bytes, dynamic) ----------------
#define SAS(s)  ((s) * 10240)                 // A: 128 rows * 80B
#define SBS(s)  (51200 + (s) * 20480)         // B: 256 rows * 80B
#define SM_B1S  153600                        // 256 f32
#define SM_W2S  154624                        // 256*4 f32
#define SM_RED  158720                        // 8 warps * 64 rows * 4 f32 = 8KB
#define SM_TOT  166912

// ---------------- device scratch ----------------
__device__ int g_odd_or;
__device__ int g_cursor[NE];
__device__ int g_off[NE + 1];
__device__ int g_perm[NE * NB];
__device__ __nv_bfloat16 g_Xh[(size_t)NB * ND];
__device__ __nv_bfloat16 g_Xl[(size_t)NB * ND];
__device__ __nv_bfloat16 g_Wh[(size_t)NE * NH * ND];   // W1^T [e][n][k]
__device__ __nv_bfloat16 g_Wl[(size_t)NE * NH * ND];
__device__ float g_partial[(size_t)NB * 16];           // [p][ntile(4)][k(4)]

// ---------------- PTX helpers (plain sm_80-era) ----------------
__device__ __forceinline__ uint32_t smem_u32(const void* p) {
    uint32_t a;
    asm("{ .reg .u64 t; cvta.to.shared.u64 t, %1; cvt.u32.u64 %0, t; }" : "=r"(a) : "l"(p));
    return a;
}
__device__ __forceinline__ void cp16(uint32_t dst, const void* src) {
    asm volatile("cp.async.cg.shared.global [%0], [%1], 16;" :: "r"(dst), "l"(src));
}
__device__ __forceinline__ void cp_commit() {
    asm volatile("cp.async.commit_group;" ::: "memory");
}
template <int N> __device__ __forceinline__ void cp_wait() {
    asm volatile("cp.async.wait_group %0;" :: "n"(N) : "memory");
}
__device__ __forceinline__ void ldsm4(uint32_t& r0, uint32_t& r1, uint32_t& r2, uint32_t& r3,
                                      uint32_t addr) {
    asm volatile("ldmatrix.sync.aligned.m8n8.x4.shared.b16 {%0,%1,%2,%3}, [%4];"
                 : "=r"(r0), "=r"(r1), "=r"(r2), "=r"(r3) : "r"(addr));
}
__device__ __forceinline__ void mma_bf16(float* d, const uint32_t* a, const uint32_t* b) {
    asm volatile(
        "mma.sync.aligned.m16n8k16.row.col.f32.bf16.bf16.f32 "
        "{%0,%1,%2,%3}, {%4,%5,%6,%7}, {%8,%9}, {%0,%1,%2,%3};"
        : "+f"(d[0]), "+f"(d[1]), "+f"(d[2]), "+f"(d[3])
        : "r"(a[0]), "r"(a[1]), "r"(a[2]), "r"(a[3]), "r"(b[0]), "r"(b[1]));
}

// ---------------- routing ----------------
// init + int64/int32 detection in one single-block kernel
__global__ __launch_bounds__(256) void k_init(const int* __restrict__ s) {
    __shared__ int flag;
    int tid = threadIdx.x;
    if (tid == 0) flag = 0;
    if (tid < NE) g_cursor[tid] = 0;
    __syncthreads();
    int v = 0;
    for (int i = tid; i < NB; i += 256) v |= s[2 * i + 1];
    unsigned any = __ballot_sync(0xFFFFFFFFu, v != 0);
    if ((tid & 31) == 0 && any) atomicOr(&flag, 1);
    __syncthreads();
    if (tid == 0) g_odd_or = flag;
}
__global__ void k_route(const int* __restrict__ s) {
    int b = blockIdx.x * blockDim.x + threadIdx.x;
    if (b >= NB) return;
    int e = (g_odd_or == 0) ? s[2 * b] : s[b];
    e &= (NE - 1);
    int pos = atomicAdd(&g_cursor[e], 1);
    g_perm[e * NB + pos] = b;
}
__global__ void k_offsets() {
    if (threadIdx.x == 0) {
        int s = 0;
        for (int e = 0; e < NE; e++) { g_off[e] = s; s += g_cursor[e]; }
        g_off[NE] = s;
    }
}

// ---------------- conversion ----------------
__global__ __launch_bounds__(128) void k_convert_x(const float* __restrict__ x) {
    int p = blockIdx.x;
    int tid = threadIdx.x;
    int e = 0;
    #pragma unroll
    for (int q = 0; q < NE - 1; q++) if (p >= g_off[q + 1]) e = q + 1;
    int tok = g_perm[e * NB + (p - g_off[e])];
    const float4* src = (const float4*)(x + (size_t)tok * ND);
    __nv_bfloat162* dh = (__nv_bfloat162*)(g_Xh + (size_t)p * ND);
    __nv_bfloat162* dl = (__nv_bfloat162*)(g_Xl + (size_t)p * ND);
    #pragma unroll
    for (int j = 0; j < 2; j++) {
        int idx = tid + j * 128;
        float4 v = __ldg(src + idx);
        __nv_bfloat16 h0 = __float2bfloat16(v.x), h1 = __float2bfloat16(v.y);
        __nv_bfloat16 h2 = __float2bfloat16(v.z), h3 = __float2bfloat16(v.w);
        __nv_bfloat16 l0 = __float2bfloat16(v.x - __bfloat162float(h0));
        __nv_bfloat16 l1 = __float2bfloat16(v.y - __bfloat162float(h1));
        __nv_bfloat16 l2 = __float2bfloat16(v.z - __bfloat162float(h2));
        __nv_bfloat16 l3 = __float2bfloat16(v.w - __bfloat162float(h3));
        dh[idx * 2 + 0] = __nv_bfloat162{h0, h1};
        dh[idx * 2 + 1] = __nv_bfloat162{h2, h3};
        dl[idx * 2 + 0] = __nv_bfloat162{l0, l1};
        dl[idx * 2 + 1] = __nv_bfloat162{l2, l3};
    }
}
__global__ __launch_bounds__(256) void k_convert_w(const float* __restrict__ W1) {
    __shared__ float t[32][33];
    int e = blockIdx.z;
    int n0 = blockIdx.x * 32, k0 = blockIdx.y * 32;
    int tx = threadIdx.x, ty = threadIdx.y;
    #pragma unroll
    for (int j = 0; j < 4; j++) {
        int k = k0 + ty + j * 8;
        t[ty + j * 8][tx] = __ldg(&W1[((size_t)e * ND + k) * NH + n0 + tx]);
    }
    __syncthreads();
    #pragma unroll
    for (int j = 0; j < 4; j++) {
        int n = n0 + ty + j * 8;
        float v = t[tx][ty + j * 8];
        __nv_bfloat16 h = __float2bfloat16(v);
        __nv_bfloat16 l = __float2bfloat16(v - __bfloat162float(h));
        size_t o = ((size_t)e * NH + n) * ND + k0 + tx;
        g_Wh[o] = h;
        g_Wl[o] = l;
    }
}

// ---------------- grouped GEMM (mma.sync bf16x3) + fused epilogue ----------------
// CTA: 128 tokens x 256 hidden for expert e; 8 warps in 2(M) x 4(N),
// warp tile 64x64, 5-stage cp.async pipeline, one sync per chunk, K' = 3072.
__global__ __launch_bounds__(256, 1) void k_gemm(const float* __restrict__ b1,
                                                 const float* __restrict__ W2) {
    const int mt = blockIdx.x, nt = blockIdx.y, e = blockIdx.z;
    const int cnt = g_cursor[e];
    if (mt * TMT >= cnt) return;

    extern __shared__ char smem[];
    const uint32_t sb = smem_u32(smem);
    const int tid = threadIdx.x;
    const int lane = tid & 31, warp = tid >> 5;
    const int wm = warp >> 2, wn = warp & 3;

    float* b1s = (float*)(smem + SM_B1S);
    float* w2s = (float*)(smem + SM_W2S);
    float* red = (float*)(smem + SM_RED);

    if (tid < 256) b1s[tid] = b1[e * NH + nt * TNT + tid];
    #pragma unroll
    for (int j = 0; j < 4; j++) {
        int idx = tid + j * 256;
        w2s[idx] = W2[((size_t)e * NH + nt * TNT) * NKM1 + idx];
    }

    const int aBase = g_off[e] + mt * TMT;
    const int bBase = e * NH + nt * TNT;

    const uint32_t aRowOff = (uint32_t)(wm * 64 + (lane & 15)) * ASTRIDE + ((lane >> 4) * 16);
    const uint32_t bRowOff = (uint32_t)(wn * 64 + (lane & 7) + ((lane >> 4) & 1) * 8) * ASTRIDE +
                             (((lane >> 3) & 1) * 16);

    float acc[4][8][4];
    #pragma unroll
    for (int i = 0; i < 4; i++)
        #pragma unroll
        for (int j = 0; j < 8; j++)
            #pragma unroll
            for (int r = 0; r < 4; r++) acc[i][j][r] = 0.0f;

    auto load_stage = [&](int c, int st) {
        const int seg = c >> 5;
        const int kc = (c & 31) << 5;
        const __nv_bfloat16* __restrict__ As = (seg == 1) ? g_Xl : g_Xh;
        const __nv_bfloat16* __restrict__ Bs = (seg == 2) ? g_Wl : g_Wh;
        // A: 128 rows x 64B = 512 cp16
        #pragma unroll
        for (int j = 0; j < 2; j++) {
            int idx = tid + j * 256;
            int row = idx >> 2, ch = idx & 3;
            int gr = aBase + row; if (gr > NB - 1) gr = NB - 1;
            cp16(sb + SAS(st) + row * ASTRIDE + ch * 16,
                 As + (size_t)gr * ND + kc + ch * 8);
        }
        // B: 256 rows x 64B = 1024 cp16
        #pragma unroll
        for (int j = 0; j < 4; j++) {
            int idx = tid + j * 256;
            int row = idx >> 2, ch = idx & 3;
            cp16(sb + SBS(st) + row * ASTRIDE + ch * 16,
                 Bs + (size_t)(bBase + row) * ND + kc + ch * 8);
        }
    };

    #pragma unroll
    for (int c = 0; c < STAGES - 1; c++) { load_stage(c, c); cp_commit(); }

    int st = 0;
    for (int c = 0; c < NCH; c++) {
        cp_wait<STAGES - 2>();
        __syncthreads();
        const uint32_t sA = sb + SAS(st), sBt = sb + SBS(st);

        #pragma unroll
        for (int ks = 0; ks < 2; ks++) {
            uint32_t bf[8][2];
            #pragma unroll
            for (int ntp = 0; ntp < 4; ntp++)
                ldsm4(bf[2 * ntp][0], bf[2 * ntp][1], bf[2 * ntp + 1][0], bf[2 * ntp + 1][1],
                      sBt + bRowOff + ntp * (16 * ASTRIDE) + ks * 32);
            uint32_t af[4][4];
            #pragma unroll
            for (int m = 0; m < 4; m++)
                ldsm4(af[m][0], af[m][1], af[m][2], af[m][3],
                      sA + aRowOff + m * (16 * ASTRIDE) + ks * 32);
            #pragma unroll
            for (int m = 0; m < 4; m++)
                #pragma unroll
                for (int n = 0; n < 8; n++)
                    mma_bf16(acc[m][n], af[m], bf[n]);
        }

        if (c + STAGES - 1 < NCH) load_stage(c + STAGES - 1, (c + STAGES - 1) % STAGES);
        cp_commit();
        st = (st + 1 == STAGES) ? 0 : st + 1;
    }
    cp_wait<0>();

    // ---------- fused epilogue: bias + relu + W2 contraction ----------
    #pragma unroll
    for (int m = 0; m < 4; m++) {
        float pr[2][4] = {{0.f, 0.f, 0.f, 0.f}, {0.f, 0.f, 0.f, 0.f}};
        #pragma unroll
        for (int n = 0; n < 8; n++) {
            #pragma unroll
            for (int r = 0; r < 4; r++) {
                int col = wn * 64 + n * 8 + 2 * (lane & 3) + (r & 1);
                float v = acc[m][n][r] + b1s[col];
                v = fmaxf(v, 0.0f);
                int half = r >> 1;
                #pragma unroll
                for (int k = 0; k < 4; k++) pr[half][k] += v * w2s[col * 4 + k];
            }
        }
        #pragma unroll
        for (int h = 0; h < 2; h++)
            #pragma unroll
            for (int k = 0; k < 4; k++) {
                pr[h][k] += __shfl_xor_sync(0xFFFFFFFFu, pr[h][k], 1);
                pr[h][k] += __shfl_xor_sync(0xFFFFFFFFu, pr[h][k], 2);
            }
        if ((lane & 3) == 0) {
            int r0 = m * 16 + (lane >> 2);
            float* dst0 = &red[(((wm * 4 + wn) * 64) + r0) * 4];
            float* dst1 = &red[(((wm * 4 + wn) * 64) + r0 + 8) * 4];
            #pragma unroll
            for (int k = 0; k < 4; k++) { dst0[k] = pr[0][k]; dst1[k] = pr[1][k]; }
        }
    }
    __syncthreads();

    // cross-warp(N) reduction + deterministic partial store
    #pragma unroll
    for (int j = 0; j < 2; j++) {
        int idx = tid + j * 256;          // (row 0..127, k 0..3)
        int row = idx >> 2, k = idx & 3;
        int wmr = row >> 6, r64 = row & 63;
        float s = 0.f;
        #pragma unroll
        for (int w = 0; w < 4; w++) s += red[(((wmr * 4 + w) * 64) + r64) * 4 + k];
        if (mt * TMT + row < cnt) {
            int p = aBase + row;
            g_partial[(size_t)p * 16 + nt * 4 + k] = s;
        }
    }
}

// ---------------- final reduction + ordinal head ----------------
__global__ __launch_bounds__(256) void k_final(const float* __restrict__ b2,
                                               float* __restrict__ out) {
    int p = blockIdx.x * blockDim.x + threadIdx.x;
    if (p >= NB) return;
    int e = 0;
    #pragma unroll
    for (int q = 0; q < NE - 1; q++) if (p >= g_off[q + 1]) e = q + 1;
    int tok = g_perm[e * NB + (p - g_off[e])];

    float lg[NKM1];
    #pragma unroll
    for (int k = 0; k < NKM1; k++) {
        float s = b2[e * NKM1 + k];
        #pragma unroll
        for (int ntl = 0; ntl < 4; ntl++) s += g_partial[(size_t)p * 16 + ntl * 4 + k];
        lg[k] = s;
        out[(size_t)tok * NKM1 + k] = s;
    }
    float q0 = 1.0f / (1.0f + expf(-lg[0]));
    float q1 = 1.0f / (1.0f + expf(-lg[1]));
    float q2 = 1.0f / (1.0f + expf(-lg[2]));
    float q3 = 1.0f / (1.0f + expf(-lg[3]));
    float pr[NK];
    pr[0] = 1.0f - q0; pr[1] = q0 - q1; pr[2] = q1 - q2; pr[3] = q2 - q3; pr[4] = q3;
    float ssum = 0.0f;
    #pragma unroll
    for (int k = 0; k < NK; k++) { pr[k] = fmaxf(pr[k], EPSV); ssum += pr[k]; }
    ssum = fmaxf(ssum, EPSV);
    float inv = 1.0f / ssum;
    float* po = out + (size_t)NB * NKM1 + (size_t)tok * NK;
    #pragma unroll
    for (int k = 0; k < NK; k++) po[k] = pr[k] * inv;
}

// ---------------- launch ----------------
extern "C" void kernel_launch(void* const* d_in, const int* in_sizes, int n_in,
                              void* d_out, int out_size) {
    const float* x    = (const float*)d_in[0];
    const int*   sidx = (const int*)d_in[1];
    const float* W1   = (const float*)d_in[2];
    const float* b1   = (const float*)d_in[3];
    const float* W2   = (const float*)d_in[4];
    const float* b2   = (const float*)d_in[5];
    float* out = (float*)d_out;

    cudaFuncSetAttribute(k_gemm, cudaFuncAttributeMaxDynamicSharedMemorySize, SM_TOT);

    k_init<<<1, 256>>>(sidx);
    k_route<<<32, 256>>>(sidx);
    k_offsets<<<1, 32>>>();
    k_convert_x<<<NB, 128>>>(x);
    k_convert_w<<<dim3(32, 32, 8), dim3(32, 8)>>>(W1);
    k_gemm<<<dim3(NB / TMT, NH / TNT, NE), 256, SM_TOT>>>(b1, W2);
    k_final<<<NB / 256, 256>>>(b2, out);
}

// round 9
// speedup vs baseline: 13.8061x; 1.5548x over previous
#include <cuda_runtime.h>
#include <cuda_fp16.h>
#include <cstdint>

// ---------------- problem constants ----------------
#define NB 8192
#define ND 1024
#define NH 1024
#define NE 8
#define NK 5
#define NKM1 4
#define EPSV 1e-8f

// ---------------- GEMM tiling ----------------
#define TMT 128          // token tile (M)
#define TNT 256          // hidden tile (N)
#define NCH 32           // K chunks of 32 (K = 1024; A hi/lo both use same B chunk)
#define STAGES 4
#define ASTRIDE 80       // padded smem row stride (bytes)

// ---------------- smem layout (bytes, dynamic) ----------------
// stage: B (256 rows x 80B) | Ah (128 x 80B) | Al (128 x 80B) = 40960B
#define SBS(s)  ((s) * 40960)
#define SAH(s)  ((s) * 40960 + 20480)
#define SAL(s)  ((s) * 40960 + 30720)
#define SM_B1S  163840                        // 256 f32
#define SM_W2S  164864                        // 256*4 f32
#define SM_RED  168960                        // 8 warps * 64 rows * 4 f32 = 8KB
#define SM_TOT  177152

// ---------------- device scratch ----------------
__device__ int g_odd_or;
__device__ int g_cursor[NE];
__device__ int g_off[NE + 1];
__device__ int g_perm[NE * NB];
__device__ __half g_Xh[(size_t)NB * ND];
__device__ __half g_Xl[(size_t)NB * ND];
__device__ __half g_Wh[(size_t)NE * NH * ND];   // W1^T [e][n][k], fp16
__device__ float g_partial[(size_t)NB * 16];    // [p][ntile(4)][k(4)]

// ---------------- PTX helpers (plain sm_80-era) ----------------
__device__ __forceinline__ uint32_t smem_u32(const void* p) {
    uint32_t a;
    asm("{ .reg .u64 t; cvta.to.shared.u64 t, %1; cvt.u32.u64 %0, t; }" : "=r"(a) : "l"(p));
    return a;
}
__device__ __forceinline__ void cp16(uint32_t dst, const void* src) {
    asm volatile("cp.async.cg.shared.global [%0], [%1], 16;" :: "r"(dst), "l"(src));
}
__device__ __forceinline__ void cp_commit() {
    asm volatile("cp.async.commit_group;" ::: "memory");
}
template <int N> __device__ __forceinline__ void cp_wait() {
    asm volatile("cp.async.wait_group %0;" :: "n"(N) : "memory");
}
__device__ __forceinline__ void ldsm4(uint32_t& r0, uint32_t& r1, uint32_t& r2, uint32_t& r3,
                                      uint32_t addr) {
    asm volatile("ldmatrix.sync.aligned.m8n8.x4.shared.b16 {%0,%1,%2,%3}, [%4];"
                 : "=r"(r0), "=r"(r1), "=r"(r2), "=r"(r3) : "r"(addr));
}
__device__ __forceinline__ void mma_fp16(float* d, const uint32_t* a, const uint32_t* b) {
    asm volatile(
        "mma.sync.aligned.m16n8k16.row.col.f32.f16.f16.f32 "
        "{%0,%1,%2,%3}, {%4,%5,%6,%7}, {%8,%9}, {%0,%1,%2,%3};"
        : "+f"(d[0]), "+f"(d[1]), "+f"(d[2]), "+f"(d[3])
        : "r"(a[0]), "r"(a[1]), "r"(a[2]), "r"(a[3]), "r"(b[0]), "r"(b[1]));
}

// ---------------- routing ----------------
__global__ __launch_bounds__(256) void k_init(const int* __restrict__ s) {
    __shared__ int flag;
    int tid = threadIdx.x;
    if (tid == 0) flag = 0;
    if (tid < NE) g_cursor[tid] = 0;
    __syncthreads();
    int v = 0;
    for (int i = tid; i < NB; i += 256) v |= s[2 * i + 1];
    unsigned any = __ballot_sync(0xFFFFFFFFu, v != 0);
    if ((tid & 31) == 0 && any) atomicOr(&flag, 1);
    __syncthreads();
    if (tid == 0) g_odd_or = flag;
}
__global__ void k_route(const int* __restrict__ s) {
    int b = blockIdx.x * blockDim.x + threadIdx.x;
    if (b >= NB) return;
    int e = (g_odd_or == 0) ? s[2 * b] : s[b];
    e &= (NE - 1);
    int pos = atomicAdd(&g_cursor[e], 1);
    g_perm[e * NB + pos] = b;
}
__global__ void k_offsets() {
    if (threadIdx.x == 0) {
        int s = 0;
        for (int e = 0; e < NE; e++) { g_off[e] = s; s += g_cursor[e]; }
        g_off[NE] = s;
    }
}

// ---------------- conversion ----------------
// Gather token rows in expert order; fp16 hi + fp16 residual.
__global__ __launch_bounds__(128) void k_convert_x(const float* __restrict__ x) {
    int p = blockIdx.x;
    int tid = threadIdx.x;
    int e = 0;
    #pragma unroll
    for (int q = 0; q < NE - 1; q++) if (p >= g_off[q + 1]) e = q + 1;
    int tok = g_perm[e * NB + (p - g_off[e])];
    const float4* src = (const float4*)(x + (size_t)tok * ND);
    __half2* dh = (__half2*)(g_Xh + (size_t)p * ND);
    __half2* dl = (__half2*)(g_Xl + (size_t)p * ND);
    #pragma unroll
    for (int j = 0; j < 2; j++) {
        int idx = tid + j * 128;
        float4 v = __ldg(src + idx);
        __half h0 = __float2half_rn(v.x), h1 = __float2half_rn(v.y);
        __half h2 = __float2half_rn(v.z), h3 = __float2half_rn(v.w);
        __half l0 = __float2half_rn(v.x - __half2float(h0));
        __half l1 = __float2half_rn(v.y - __half2float(h1));
        __half l2 = __float2half_rn(v.z - __half2float(h2));
        __half l3 = __float2half_rn(v.w - __half2float(h3));
        dh[idx * 2 + 0] = __half2{h0, h1};
        dh[idx * 2 + 1] = __half2{h2, h3};
        dl[idx * 2 + 0] = __half2{l0, l1};
        dl[idx * 2 + 1] = __half2{l2, l3};
    }
}
// Transpose W1[e][k][n] -> [e][n][k], single fp16.
__global__ __launch_bounds__(256) void k_convert_w(const float* __restrict__ W1) {
    __shared__ float t[32][33];
    int e = blockIdx.z;
    int n0 = blockIdx.x * 32, k0 = blockIdx.y * 32;
    int tx = threadIdx.x, ty = threadIdx.y;
    #pragma unroll
    for (int j = 0; j < 4; j++) {
        int k = k0 + ty + j * 8;
        t[ty + j * 8][tx] = __ldg(&W1[((size_t)e * ND + k) * NH + n0 + tx]);
    }
    __syncthreads();
    #pragma unroll
    for (int j = 0; j < 4; j++) {
        int n = n0 + ty + j * 8;
        g_Wh[((size_t)e * NH + n) * ND + k0 + tx] = __float2half_rn(t[tx][ty + j * 8]);
    }
}

// ---------------- grouped GEMM (mma.sync fp16, A hi/lo) + fused epilogue ----------------
// CTA: 128 tokens x 256 hidden for expert e; 8 warps (2 M x 4 N), warp tile 64x64.
// Per K-chunk (32 wide): load B once, run two MMA passes (Ah*B, Al*B).
__global__ __launch_bounds__(256, 1) void k_gemm(const float* __restrict__ b1,
                                                 const float* __restrict__ W2) {
    const int mt = blockIdx.x, nt = blockIdx.y, e = blockIdx.z;
    const int cnt = g_cursor[e];
    if (mt * TMT >= cnt) return;

    extern __shared__ char smem[];
    const uint32_t sb = smem_u32(smem);
    const int tid = threadIdx.x;
    const int lane = tid & 31, warp = tid >> 5;
    const int wm = warp >> 2, wn = warp & 3;

    float* b1s = (float*)(smem + SM_B1S);
    float* w2s = (float*)(smem + SM_W2S);
    float* red = (float*)(smem + SM_RED);

    b1s[tid] = b1[e * NH + nt * TNT + tid];
    #pragma unroll
    for (int j = 0; j < 4; j++) {
        int idx = tid + j * 256;
        w2s[idx] = W2[((size_t)e * NH + nt * TNT) * NKM1 + idx];
    }

    const int aBase = g_off[e] + mt * TMT;
    const int bBase = e * NH + nt * TNT;

    const uint32_t aRowOff = (uint32_t)(wm * 64 + (lane & 15)) * ASTRIDE + ((lane >> 4) * 16);
    const uint32_t bRowOff = (uint32_t)(wn * 64 + (lane & 7) + ((lane >> 4) & 1) * 8) * ASTRIDE +
                             (((lane >> 3) & 1) * 16);

    float acc[4][8][4];
    #pragma unroll
    for (int i = 0; i < 4; i++)
        #pragma unroll
        for (int j = 0; j < 8; j++)
            #pragma unroll
            for (int r = 0; r < 4; r++) acc[i][j][r] = 0.0f;

    auto load_stage = [&](int c, int st) {
        const int kc = c << 5;
        // B: 256 rows x 64B = 1024 cp16
        #pragma unroll
        for (int j = 0; j < 4; j++) {
            int idx = tid + j * 256;
            int row = idx >> 2, ch = idx & 3;
            cp16(sb + SBS(st) + row * ASTRIDE + ch * 16,
                 g_Wh + (size_t)(bBase + row) * ND + kc + ch * 8);
        }
        // Ah + Al: 128 rows x 64B each
        #pragma unroll
        for (int j = 0; j < 2; j++) {
            int idx = tid + j * 256;
            int row = idx >> 2, ch = idx & 3;
            int gr = aBase + row; if (gr > NB - 1) gr = NB - 1;
            cp16(sb + SAH(st) + row * ASTRIDE + ch * 16,
                 g_Xh + (size_t)gr * ND + kc + ch * 8);
            cp16(sb + SAL(st) + row * ASTRIDE + ch * 16,
                 g_Xl + (size_t)gr * ND + kc + ch * 8);
        }
    };

    #pragma unroll
    for (int c = 0; c < STAGES - 1; c++) { load_stage(c, c); cp_commit(); }

    int st = 0;
    for (int c = 0; c < NCH; c++) {
        cp_wait<STAGES - 2>();
        __syncthreads();
        const uint32_t sB = sb + SBS(st), sAh = sb + SAH(st), sAl = sb + SAL(st);

        #pragma unroll
        for (int ks = 0; ks < 2; ks++) {
            uint32_t bf[8][2];
            #pragma unroll
            for (int ntp = 0; ntp < 4; ntp++)
                ldsm4(bf[2 * ntp][0], bf[2 * ntp][1], bf[2 * ntp + 1][0], bf[2 * ntp + 1][1],
                      sB + bRowOff + ntp * (16 * ASTRIDE) + ks * 32);
            uint32_t af[4][4];
            // pass 1: Ah
            #pragma unroll
            for (int m = 0; m < 4; m++)
                ldsm4(af[m][0], af[m][1], af[m][2], af[m][3],
                      sAh + aRowOff + m * (16 * ASTRIDE) + ks * 32);
            #pragma unroll
            for (int m = 0; m < 4; m++)
                #pragma unroll
                for (int n = 0; n < 8; n++)
                    mma_fp16(acc[m][n], af[m], bf[n]);
            // pass 2: Al (B fragments reused)
            #pragma unroll
            for (int m = 0; m < 4; m++)
                ldsm4(af[m][0], af[m][1], af[m][2], af[m][3],
                      sAl + aRowOff + m * (16 * ASTRIDE) + ks * 32);
            #pragma unroll
            for (int m = 0; m < 4; m++)
                #pragma unroll
                for (int n = 0; n < 8; n++)
                    mma_fp16(acc[m][n], af[m], bf[n]);
        }

        if (c + STAGES - 1 < NCH) load_stage(c + STAGES - 1, (c + STAGES - 1) % STAGES);
        cp_commit();
        st = (st + 1 == STAGES) ? 0 : st + 1;
    }
    cp_wait<0>();

    // ---------- fused epilogue: bias + relu + W2 contraction ----------
    #pragma unroll
    for (int m = 0; m < 4; m++) {
        float pr[2][4] = {{0.f, 0.f, 0.f, 0.f}, {0.f, 0.f, 0.f, 0.f}};
        #pragma unroll
        for (int n = 0; n < 8; n++) {
            #pragma unroll
            for (int r = 0; r < 4; r++) {
                int col = wn * 64 + n * 8 + 2 * (lane & 3) + (r & 1);
                float v = acc[m][n][r] + b1s[col];
                v = fmaxf(v, 0.0f);
                int half = r >> 1;
                #pragma unroll
                for (int k = 0; k < 4; k++) pr[half][k] += v * w2s[col * 4 + k];
            }
        }
        #pragma unroll
        for (int h = 0; h < 2; h++)
            #pragma unroll
            for (int k = 0; k < 4; k++) {
                pr[h][k] += __shfl_xor_sync(0xFFFFFFFFu, pr[h][k], 1);
                pr[h][k] += __shfl_xor_sync(0xFFFFFFFFu, pr[h][k], 2);
            }
        if ((lane & 3) == 0) {
            int r0 = m * 16 + (lane >> 2);
            float* dst0 = &red[(((wm * 4 + wn) * 64) + r0) * 4];
            float* dst1 = &red[(((wm * 4 + wn) * 64) + r0 + 8) * 4];
            #pragma unroll
            for (int k = 0; k < 4; k++) { dst0[k] = pr[0][k]; dst1[k] = pr[1][k]; }
        }
    }
    __syncthreads();

    // cross-warp(N) reduction + deterministic partial store
    #pragma unroll
    for (int j = 0; j < 2; j++) {
        int idx = tid + j * 256;          // (row 0..127, k 0..3)
        int row = idx >> 2, k = idx & 3;
        int wmr = row >> 6, r64 = row & 63;
        float s = 0.f;
        #pragma unroll
        for (int w = 0; w < 4; w++) s += red[(((wmr * 4 + w) * 64) + r64) * 4 + k];
        if (mt * TMT + row < cnt) {
            int p = aBase + row;
            g_partial[(size_t)p * 16 + nt * 4 + k] = s;
        }
    }
}

// ---------------- final reduction + ordinal head ----------------
__global__ __launch_bounds__(256) void k_final(const float* __restrict__ b2,
                                               float* __restrict__ out) {
    int p = blockIdx.x * blockDim.x + threadIdx.x;
    if (p >= NB) return;
    int e = 0;
    #pragma unroll
    for (int q = 0; q < NE - 1; q++) if (p >= g_off[q + 1]) e = q + 1;
    int tok = g_perm[e * NB + (p - g_off[e])];

    float lg[NKM1];
    #pragma unroll
    for (int k = 0; k < NKM1; k++) {
        float s = b2[e * NKM1 + k];
        #pragma unroll
        for (int ntl = 0; ntl < 4; ntl++) s += g_partial[(size_t)p * 16 + ntl * 4 + k];
        lg[k] = s;
        out[(size_t)tok * NKM1 + k] = s;
    }
    float q0 = 1.0f / (1.0f + expf(-lg[0]));
    float q1 = 1.0f / (1.0f + expf(-lg[1]));
    float q2 = 1.0f / (1.0f + expf(-lg[2]));
    float q3 = 1.0f / (1.0f + expf(-lg[3]));
    float pr[NK];
    pr[0] = 1.0f - q0; pr[1] = q0 - q1; pr[2] = q1 - q2; pr[3] = q2 - q3; pr[4] = q3;
    float ssum = 0.0f;
    #pragma unroll
    for (int k = 0; k < NK; k++) { pr[k] = fmaxf(pr[k], EPSV); ssum += pr[k]; }
    ssum = fmaxf(ssum, EPSV);
    float inv = 1.0f / ssum;
    float* po = out + (size_t)NB * NKM1 + (size_t)tok * NK;
    #pragma unroll
    for (int k = 0; k < NK; k++) po[k] = pr[k] * inv;
}

// ---------------- launch ----------------
extern "C" void kernel_launch(void* const* d_in, const int* in_sizes, int n_in,
                              void* d_out, int out_size) {
    const float* x    = (const float*)d_in[0];
    const int*   sidx = (const int*)d_in[1];
    const float* W1   = (const float*)d_in[2];
    const float* b1   = (const float*)d_in[3];
    const float* W2   = (const float*)d_in[4];
    const float* b2   = (const float*)d_in[5];
    float* out = (float*)d_out;

    cudaFuncSetAttribute(k_gemm, cudaFuncAttributeMaxDynamicSharedMemorySize, SM_TOT);

    k_init<<<1, 256>>>(sidx);
    k_route<<<32, 256>>>(sidx);
    k_offsets<<<1, 32>>>();
    k_convert_x<<<NB, 128>>>(x);
    k_convert_w<<<dim3(32, 32, 8), dim3(32, 8)>>>(W1);
    k_gemm<<<dim3(NB / TMT, NH / TNT, NE), 256, SM_TOT>>>(b1, W2);
    k_final<<<NB / 256, 256>>>(b2, out);
}